// round 6
// baseline (speedup 1.0000x reference)
#include <cuda_runtime.h>

// ---------------------------------------------------------------------------
// SwinTransformerBlock3D: DIM=96, HEADS=6, hd=16, WIN=4x4x4 (N=64), SHIFT=2,
// GRID=(16,64,64), B=2.  Shift == cyclic index remap (no mask needed).
// f32x2 packed FMA, 8x6 register tiles, float4 A-caching (4-row waves).
// ---------------------------------------------------------------------------

#define NWIN 2048
#define NTOK 131072
#define DIMC 96
#define HP2 100            // padded row stride: 16B-aligned, conflict-free

typedef unsigned long long u64;

__device__ __forceinline__ u64 pk2(float x, float y) {
    u64 r;
    asm("mov.b64 %0, {%1, %2};" : "=l"(r)
        : "r"(__float_as_uint(x)), "r"(__float_as_uint(y)));
    return r;
}
__device__ __forceinline__ void upk2(u64 v, float& x, float& y) {
    unsigned int a, b;
    asm("mov.b64 {%0, %1}, %2;" : "=r"(a), "=r"(b) : "l"(v));
    x = __uint_as_float(a); y = __uint_as_float(b);
}
__device__ __forceinline__ void fma2(u64& d, u64 a, u64 b) {
    asm("fma.rn.f32x2 %0, %1, %2, %0;" : "+l"(d) : "l"(a), "l"(b));
}
__device__ __forceinline__ void add2(u64& d, u64 a, u64 b) {
    asm("add.rn.f32x2 %0, %1, %2;" : "=l"(d) : "l"(a), "l"(b));
}

// Scratch
__device__ float g_q [NWIN * 64 * DIMC];
__device__ float g_k [NWIN * 64 * DIMC];
__device__ float g_v [NWIN * 64 * DIMC];
__device__ float g_ow[NWIN * 64 * DIMC];
__device__ float g_x1[NTOK * DIMC];

#define K1_SMEM_BYTES ((64 * HP2 + 96 * 96) * 4)
#define K3_SMEM_BYTES ((64 * HP2 + 96 * 96) * 4)
#define K4_SMEM_BYTES ((2 * 64 * HP2 + 96 * 96) * 4)

// 8x6 microtile GEMM inner: acc[8][3] += A(8 rows) x B(6 cols), K=96.
// A cached in two 4-row float4 waves to bound live registers.
__device__ __forceinline__ void gemm8x6_k96(
    u64 acc[8][3], const float* __restrict__ As, int r0,
    const float* __restrict__ ws, int c0)
{
    #pragma unroll 4
    for (int k4 = 0; k4 < 24; k4++) {
        #pragma unroll
        for (int half = 0; half < 2; half++) {
            float4 a4[4];
            #pragma unroll
            for (int i = 0; i < 4; i++)
                a4[i] = *(const float4*)&As[(r0 + half * 4 + i) * HP2 + k4 * 4];
            #pragma unroll
            for (int kk = 0; kk < 4; kk++) {
                const u64* wr = (const u64*)&ws[(k4 * 4 + kk) * 96 + c0];
                const u64 b0 = wr[0], b1 = wr[1], b2 = wr[2];
                #pragma unroll
                for (int i = 0; i < 4; i++) {
                    const float a = ((const float*)&a4[i])[kk];
                    const u64 pa = pk2(a, a);
                    fma2(acc[half * 4 + i][0], pa, b0);
                    fma2(acc[half * 4 + i][1], pa, b1);
                    fma2(acc[half * 4 + i][2], pa, b2);
                }
            }
        }
    }
}

// ---------------------------------------------------------------------------
// K1: LN1 + shift gather + QKV GEMM (64x288, K=96). 1 block/window, 128 thr.
// ---------------------------------------------------------------------------
__global__ __launch_bounds__(128) void k1_ln_qkv(
    const float* __restrict__ x,
    const float* __restrict__ g1, const float* __restrict__ b1,
    const float* __restrict__ qkvw, const float* __restrict__ qkvb)
{
    extern __shared__ float dsm[];
    float* hs = dsm;               // [64][HP2]
    float* ws = dsm + 64 * HP2;    // [96][96]

    const int tid  = threadIdx.x;
    const int lane = tid & 31;
    const int wrp  = tid >> 5;
    const int win  = blockIdx.x;
    const int b  = win >> 10;
    const int r  = win & 1023;
    const int wi = r >> 8, wx = (r >> 4) & 15, wt = r & 15;

    const float gv0 = g1[lane], gv1 = g1[lane + 32], gv2 = g1[lane + 64];
    const float bb0 = b1[lane], bb1 = b1[lane + 32], bb2 = b1[lane + 64];

    for (int j = 0; j < 16; j++) {
        const int n  = wrp * 16 + j;
        const int ii = n >> 4, xx = (n >> 2) & 3, tt = n & 3;
        const int gi = (wi * 4 + ii + 2) & 15;
        const int gx = (wx * 4 + xx + 2) & 63;
        const int gt = (wt * 4 + tt + 2) & 63;
        const int tok = b * 65536 + (gi * 64 + gx) * 64 + gt;
        const float* row = x + tok * 96;
        float v0 = row[lane], v1 = row[lane + 32], v2 = row[lane + 64];
        float s = v0 + v1 + v2;
        float q = v0 * v0 + v1 * v1 + v2 * v2;
        #pragma unroll
        for (int o = 16; o > 0; o >>= 1) {
            s += __shfl_xor_sync(0xffffffffu, s, o);
            q += __shfl_xor_sync(0xffffffffu, q, o);
        }
        const float mean = s * (1.0f / 96.0f);
        const float var  = q * (1.0f / 96.0f) - mean * mean;
        const float rstd = rsqrtf(var + 1e-5f);
        hs[n * HP2 + lane]      = (v0 - mean) * rstd * gv0 + bb0;
        hs[n * HP2 + lane + 32] = (v1 - mean) * rstd * gv1 + bb1;
        hs[n * HP2 + lane + 64] = (v2 - mean) * rstd * gv2 + bb2;
    }
    __syncthreads();

    const int r0 = (tid >> 4) * 8;   // 8 row-groups x 8 rows
    const int c0 = (tid & 15) * 6;   // 16 col-groups x 6 cols

    for (int cc = 0; cc < 3; cc++) {          // q, k, v (96 cols each)
        for (int idx = tid; idx < 2304; idx += 128) {
            const int row = idx / 24, c4 = idx % 24;
            *(float4*)&ws[row * 96 + c4 * 4] =
                *(const float4*)(qkvw + row * 288 + cc * 96 + c4 * 4);
        }
        __syncthreads();

        u64 acc[8][3];
        #pragma unroll
        for (int i = 0; i < 8; i++)
            #pragma unroll
            for (int j = 0; j < 3; j++) acc[i][j] = 0ull;

        gemm8x6_k96(acc, hs, r0, ws, c0);

        float* dst = (cc == 0) ? g_q : (cc == 1) ? g_k : g_v;
        #pragma unroll
        for (int i = 0; i < 8; i++) {
            float* drow = dst + (win * 64 + r0 + i) * 96 + c0;
            #pragma unroll
            for (int jp = 0; jp < 3; jp++) {
                float ax, ay; upk2(acc[i][jp], ax, ay);
                drow[2 * jp]     = ax + qkvb[cc * 96 + c0 + 2 * jp];
                drow[2 * jp + 1] = ay + qkvb[cc * 96 + c0 + 2 * jp + 1];
            }
        }
        __syncthreads();
    }
}

// ---------------------------------------------------------------------------
// K2: windowed attention, 1 block/(window,head), 64 threads.
// ---------------------------------------------------------------------------
__global__ __launch_bounds__(64) void k2_attn(const float* __restrict__ btab)
{
    __shared__ float sq[64 * 16], sk[64 * 16], sv[64 * 16];
    __shared__ float ss[64 * 65];
    __shared__ float stab[343 * 6];

    const int n    = threadIdx.x;
    const int win  = blockIdx.x / 6;
    const int head = blockIdx.x % 6;
    const int base = win * 64 * 96 + head * 16;

    #pragma unroll
    for (int j = 0; j < 4; j++) {
        ((float4*)sq)[n * 4 + j] = ((const float4*)(g_q + base + n * 96))[j];
        ((float4*)sk)[n * 4 + j] = ((const float4*)(g_k + base + n * 96))[j];
        ((float4*)sv)[n * 4 + j] = ((const float4*)(g_v + base + n * 96))[j];
    }
    for (int i = n; i < 2058; i += 64) stab[i] = btab[i];
    __syncthreads();

    u64 qp[8];
    {
        const u64* qq = (const u64*)(sq + n * 16);
        #pragma unroll
        for (int j = 0; j < 8; j++) qp[j] = qq[j];
    }
    const int iin = n >> 4, xn = (n >> 2) & 3, tn = n & 3;
    float* myrow = &ss[n * 65];

    #pragma unroll 8
    for (int m = 0; m < 64; m++) {
        const ulonglong2* kp = (const ulonglong2*)(sk + m * 16);
        u64 sa = 0ull, sb = 0ull;
        #pragma unroll
        for (int j = 0; j < 4; j++) {
            const ulonglong2 kv = kp[j];
            fma2(sa, qp[2 * j],     kv.x);
            fma2(sb, qp[2 * j + 1], kv.y);
        }
        u64 st; add2(st, sa, sb);
        float sx, sy; upk2(st, sx, sy);
        const float s = sx + sy;
        const int im = m >> 4, xm = (m >> 2) & 3, tm = m & 3;
        const int rel = ((iin - im + 3) * 7 + (xn - xm + 3)) * 7 + (tn - tm + 3);
        myrow[m] = s * 0.25f + stab[rel * 6 + head];
    }

    float mx = -1e30f;
    #pragma unroll
    for (int m = 0; m < 64; m++) mx = fmaxf(mx, myrow[m]);
    float sum = 0.0f;
    #pragma unroll 8
    for (int m = 0; m < 64; m++) {
        const float p = __expf(myrow[m] - mx);
        myrow[m] = p;
        sum += p;
    }
    const float inv = 1.0f / sum;

    u64 ov[8];
    #pragma unroll
    for (int j = 0; j < 8; j++) ov[j] = 0ull;
    #pragma unroll 8
    for (int m = 0; m < 64; m++) {
        const float p = myrow[m];
        const u64 pp = pk2(p, p);
        const ulonglong2* vp = (const ulonglong2*)(sv + m * 16);
        #pragma unroll
        for (int j = 0; j < 4; j++) {
            const ulonglong2 vv = vp[j];
            fma2(ov[2 * j],     pp, vv.x);
            fma2(ov[2 * j + 1], pp, vv.y);
        }
    }
    float* od = g_ow + base + n * 96;
    #pragma unroll
    for (int j = 0; j < 8; j++) {
        float oxv, oyv; upk2(ov[j], oxv, oyv);
        od[2 * j]     = oxv * inv;
        od[2 * j + 1] = oyv * inv;
    }
}

// ---------------------------------------------------------------------------
// K3: proj GEMM (64x96, K=96) + window reverse + un-shift + residual.
// ---------------------------------------------------------------------------
__global__ __launch_bounds__(128) void k3_proj(
    const float* __restrict__ x,
    const float* __restrict__ pw, const float* __restrict__ pb)
{
    extern __shared__ float dsm[];
    float* os = dsm;               // [64][HP2]
    float* ws = dsm + 64 * HP2;    // [96][96]

    const int tid = threadIdx.x;
    const int win = blockIdx.x;

    for (int idx = tid; idx < 1536; idx += 128) {
        const float4 v = ((const float4*)(g_ow + win * 64 * 96))[idx];
        const int row = idx / 24, c4 = idx % 24;
        *(float4*)&os[row * HP2 + c4 * 4] = v;
    }
    for (int idx = tid; idx < 2304; idx += 128) {
        const int row = idx / 24, c4 = idx % 24;
        *(float4*)&ws[row * 96 + c4 * 4] =
            *(const float4*)(pw + row * 96 + c4 * 4);
    }

    const int b = win >> 10, r = win & 1023;
    const int wi = r >> 8, wx = (r >> 4) & 15, wt = r & 15;
    const int r0 = (tid >> 4) * 8;
    const int c0 = (tid & 15) * 6;
    __syncthreads();

    u64 acc[8][3];
    #pragma unroll
    for (int i = 0; i < 8; i++)
        #pragma unroll
        for (int j = 0; j < 3; j++) acc[i][j] = 0ull;

    gemm8x6_k96(acc, os, r0, ws, c0);

    #pragma unroll
    for (int i = 0; i < 8; i++) {
        const int n = r0 + i;
        const int ii = n >> 4, xx = (n >> 2) & 3, tt = n & 3;
        const int gi = (wi * 4 + ii + 2) & 15;
        const int gx = (wx * 4 + xx + 2) & 63;
        const int gt = (wt * 4 + tt + 2) & 63;
        const int tok = b * 65536 + (gi * 64 + gx) * 64 + gt;
        const float* xr = x + tok * 96 + c0;
        float* dr = g_x1 + tok * 96 + c0;
        #pragma unroll
        for (int jp = 0; jp < 3; jp++) {
            float ax, ay; upk2(acc[i][jp], ax, ay);
            dr[2 * jp]     = xr[2 * jp]     + ax + pb[c0 + 2 * jp];
            dr[2 * jp + 1] = xr[2 * jp + 1] + ay + pb[c0 + 2 * jp + 1];
        }
    }
}

// ---------------------------------------------------------------------------
// K4: LN2 + MLP (96->384 gelu ->96) + residual. 64 tokens/block, 128 thr.
// smem: xs[64*HP2] | hidc[64*HP2] | ws[96*96]
// ---------------------------------------------------------------------------
__global__ __launch_bounds__(128) void k4_mlp(
    const float* __restrict__ g2, const float* __restrict__ b2,
    const float* __restrict__ w1, const float* __restrict__ b1m,
    const float* __restrict__ w2, const float* __restrict__ b2m,
    float* __restrict__ out)
{
    extern __shared__ float dsm[];
    float* xs   = dsm;
    float* hidc = dsm + 64 * HP2;
    float* ws   = dsm + 2 * 64 * HP2;

    const int tid  = threadIdx.x;
    const int lane = tid & 31;
    const int wrp  = tid >> 5;
    const int t0   = blockIdx.x * 64;

    const float gv0 = g2[lane], gv1 = g2[lane + 32], gv2 = g2[lane + 64];
    const float bb0 = b2[lane], bb1 = b2[lane + 32], bb2 = b2[lane + 64];

    for (int j = 0; j < 16; j++) {
        const int rrow = wrp * 16 + j;
        const float* row = g_x1 + (t0 + rrow) * 96;
        float v0 = row[lane], v1 = row[lane + 32], v2 = row[lane + 64];
        float s = v0 + v1 + v2;
        float q = v0 * v0 + v1 * v1 + v2 * v2;
        #pragma unroll
        for (int o = 16; o > 0; o >>= 1) {
            s += __shfl_xor_sync(0xffffffffu, s, o);
            q += __shfl_xor_sync(0xffffffffu, q, o);
        }
        const float mean = s * (1.0f / 96.0f);
        const float var  = q * (1.0f / 96.0f) - mean * mean;
        const float rstd = rsqrtf(var + 1e-5f);
        xs[rrow * HP2 + lane]      = (v0 - mean) * rstd * gv0 + bb0;
        xs[rrow * HP2 + lane + 32] = (v1 - mean) * rstd * gv1 + bb1;
        xs[rrow * HP2 + lane + 64] = (v2 - mean) * rstd * gv2 + bb2;
    }
    __syncthreads();

    const int r0 = (tid >> 4) * 8;
    const int c0 = (tid & 15) * 6;

    u64 acc[8][3];
    #pragma unroll
    for (int i = 0; i < 8; i++)
        #pragma unroll
        for (int j = 0; j < 3; j++) acc[i][j] = 0ull;

    for (int hc = 0; hc < 4; hc++) {
        // load W1 chunk [96][96]
        for (int idx = tid; idx < 2304; idx += 128) {
            const int row = idx / 24, c4 = idx % 24;
            *(float4*)&ws[row * 96 + c4 * 4] =
                *(const float4*)(w1 + row * 384 + hc * 96 + c4 * 4);
        }
        __syncthreads();

        u64 ah[8][3];
        #pragma unroll
        for (int i = 0; i < 8; i++)
            #pragma unroll
            for (int j = 0; j < 3; j++) ah[i][j] = 0ull;

        gemm8x6_k96(ah, xs, r0, ws, c0);

        #pragma unroll
        for (int i = 0; i < 8; i++)
            #pragma unroll
            for (int jp = 0; jp < 3; jp++) {
                float hx, hy; upk2(ah[i][jp], hx, hy);
                hx += b1m[hc * 96 + c0 + 2 * jp];
                hy += b1m[hc * 96 + c0 + 2 * jp + 1];
                hidc[(r0 + i) * HP2 + c0 + 2 * jp] =
                    0.5f * hx * (1.0f + erff(hx * 0.70710678118654752f));
                hidc[(r0 + i) * HP2 + c0 + 2 * jp + 1] =
                    0.5f * hy * (1.0f + erff(hy * 0.70710678118654752f));
            }
        __syncthreads();

        // load W2 chunk [96][96]
        for (int idx = tid; idx < 2304; idx += 128) {
            const int row = idx / 24, c4 = idx % 24;
            *(float4*)&ws[row * 96 + c4 * 4] =
                *(const float4*)(w2 + (hc * 96 + row) * 96 + c4 * 4);
        }
        __syncthreads();

        gemm8x6_k96(acc, hidc, r0, ws, c0);
        __syncthreads();
    }

    #pragma unroll
    for (int i = 0; i < 8; i++) {
        const int tt = t0 + r0 + i;
        const float* xr = g_x1 + tt * 96 + c0;
        float* orow = out + tt * 96 + c0;
        #pragma unroll
        for (int jp = 0; jp < 3; jp++) {
            float ax, ay; upk2(acc[i][jp], ax, ay);
            orow[2 * jp]     = xr[2 * jp]     + ax + b2m[c0 + 2 * jp];
            orow[2 * jp + 1] = xr[2 * jp + 1] + ay + b2m[c0 + 2 * jp + 1];
        }
    }
}

// ---------------------------------------------------------------------------
extern "C" void kernel_launch(void* const* d_in, const int* in_sizes, int n_in,
                              void* d_out, int out_size)
{
    (void)in_sizes; (void)n_in; (void)out_size;
    const float* x     = (const float*)d_in[0];
    const float* n1g   = (const float*)d_in[1];
    const float* n1b   = (const float*)d_in[2];
    const float* qkvw  = (const float*)d_in[3];
    const float* qkvb  = (const float*)d_in[4];
    const float* projw = (const float*)d_in[5];
    const float* projb = (const float*)d_in[6];
    const float* btab  = (const float*)d_in[7];
    const float* n2g   = (const float*)d_in[8];
    const float* n2b   = (const float*)d_in[9];
    const float* w1    = (const float*)d_in[10];
    const float* b1m   = (const float*)d_in[11];
    const float* w2    = (const float*)d_in[12];
    const float* b2m   = (const float*)d_in[13];
    float* out = (float*)d_out;

    cudaFuncSetAttribute(k1_ln_qkv, cudaFuncAttributeMaxDynamicSharedMemorySize, K1_SMEM_BYTES);
    cudaFuncSetAttribute(k3_proj,   cudaFuncAttributeMaxDynamicSharedMemorySize, K3_SMEM_BYTES);
    cudaFuncSetAttribute(k4_mlp,    cudaFuncAttributeMaxDynamicSharedMemorySize, K4_SMEM_BYTES);

    k1_ln_qkv<<<NWIN, 128, K1_SMEM_BYTES>>>(x, n1g, n1b, qkvw, qkvb);
    k2_attn  <<<NWIN * 6, 64>>>(btab);
    k3_proj  <<<NWIN, 128, K3_SMEM_BYTES>>>(x, projw, projb);
    k4_mlp   <<<NTOK / 64, 128, K4_SMEM_BYTES>>>(n2g, n2b, w1, b1m, w2, b2m, out);
}

// round 13
// speedup vs baseline: 1.0602x; 1.0602x over previous
#include <cuda_runtime.h>

// ---------------------------------------------------------------------------
// SwinTransformerBlock3D: DIM=96, HEADS=6, hd=16, WIN=4x4x4 (N=64), SHIFT=2,
// GRID=(16,64,64), B=2.  Shift == cyclic index remap (no mask needed).
// f32x2 packed FMA, 4x6 register tiles, 256 threads (occupancy-tuned).
// ---------------------------------------------------------------------------

#define NWIN 2048
#define NTOK 131072
#define DIMC 96
#define HP2 100            // padded row stride: 16B-aligned, conflict-free

typedef unsigned long long u64;

__device__ __forceinline__ u64 pk2(float x, float y) {
    u64 r;
    asm("mov.b64 %0, {%1, %2};" : "=l"(r)
        : "r"(__float_as_uint(x)), "r"(__float_as_uint(y)));
    return r;
}
__device__ __forceinline__ void upk2(u64 v, float& x, float& y) {
    unsigned int a, b;
    asm("mov.b64 {%0, %1}, %2;" : "=r"(a), "=r"(b) : "l"(v));
    x = __uint_as_float(a); y = __uint_as_float(b);
}
__device__ __forceinline__ void fma2(u64& d, u64 a, u64 b) {
    asm("fma.rn.f32x2 %0, %1, %2, %0;" : "+l"(d) : "l"(a), "l"(b));
}
__device__ __forceinline__ void add2(u64& d, u64 a, u64 b) {
    asm("add.rn.f32x2 %0, %1, %2;" : "=l"(d) : "l"(a), "l"(b));
}

// Scratch
__device__ float g_q [NWIN * 64 * DIMC];
__device__ float g_k [NWIN * 64 * DIMC];
__device__ float g_v [NWIN * 64 * DIMC];
__device__ float g_ow[NWIN * 64 * DIMC];
__device__ float g_x1[NTOK * DIMC];

#define K1_SMEM_BYTES ((64 * HP2 + 96 * 96) * 4)
#define K3_SMEM_BYTES ((64 * HP2 + 96 * 96) * 4)
#define K4_SMEM_BYTES ((2 * 64 * HP2 + 96 * 96) * 4)

// 4x6 microtile GEMM inner: acc[4][3] += A(4 rows) x B(6 cols), K=96.
__device__ __forceinline__ void gemm4x6_k96(
    u64 acc[4][3], const float* __restrict__ As, int r0,
    const float* __restrict__ ws, int c0)
{
    #pragma unroll 4
    for (int k4 = 0; k4 < 24; k4++) {
        float4 a4[4];
        #pragma unroll
        for (int i = 0; i < 4; i++)
            a4[i] = *(const float4*)&As[(r0 + i) * HP2 + k4 * 4];
        #pragma unroll
        for (int kk = 0; kk < 4; kk++) {
            const u64* wr = (const u64*)&ws[(k4 * 4 + kk) * 96 + c0];
            const u64 b0 = wr[0], b1 = wr[1], b2 = wr[2];
            #pragma unroll
            for (int i = 0; i < 4; i++) {
                const float a = ((const float*)&a4[i])[kk];
                const u64 pa = pk2(a, a);
                fma2(acc[i][0], pa, b0);
                fma2(acc[i][1], pa, b1);
                fma2(acc[i][2], pa, b2);
            }
        }
    }
}

// ---------------------------------------------------------------------------
// K1: LN1 + shift gather + QKV GEMM (64x288, K=96). 1 block/window, 256 thr.
// ---------------------------------------------------------------------------
__global__ __launch_bounds__(256) void k1_ln_qkv(
    const float* __restrict__ x,
    const float* __restrict__ g1, const float* __restrict__ b1,
    const float* __restrict__ qkvw, const float* __restrict__ qkvb)
{
    extern __shared__ float dsm[];
    float* hs = dsm;               // [64][HP2]
    float* ws = dsm + 64 * HP2;    // [96][96]

    const int tid  = threadIdx.x;
    const int lane = tid & 31;
    const int wrp  = tid >> 5;     // 0..7
    const int win  = blockIdx.x;
    const int b  = win >> 10;
    const int r  = win & 1023;
    const int wi = r >> 8, wx = (r >> 4) & 15, wt = r & 15;

    const float gv0 = g1[lane], gv1 = g1[lane + 32], gv2 = g1[lane + 64];
    const float bb0 = b1[lane], bb1 = b1[lane + 32], bb2 = b1[lane + 64];

    // LN + gather: 8 warps x 8 rows
    for (int j = 0; j < 8; j++) {
        const int n  = wrp * 8 + j;
        const int ii = n >> 4, xx = (n >> 2) & 3, tt = n & 3;
        const int gi = (wi * 4 + ii + 2) & 15;
        const int gx = (wx * 4 + xx + 2) & 63;
        const int gt = (wt * 4 + tt + 2) & 63;
        const int tok = b * 65536 + (gi * 64 + gx) * 64 + gt;
        const float* row = x + tok * 96;
        float v0 = row[lane], v1 = row[lane + 32], v2 = row[lane + 64];
        float s = v0 + v1 + v2;
        float q = v0 * v0 + v1 * v1 + v2 * v2;
        #pragma unroll
        for (int o = 16; o > 0; o >>= 1) {
            s += __shfl_xor_sync(0xffffffffu, s, o);
            q += __shfl_xor_sync(0xffffffffu, q, o);
        }
        const float mean = s * (1.0f / 96.0f);
        const float var  = q * (1.0f / 96.0f) - mean * mean;
        const float rstd = rsqrtf(var + 1e-5f);
        hs[n * HP2 + lane]      = (v0 - mean) * rstd * gv0 + bb0;
        hs[n * HP2 + lane + 32] = (v1 - mean) * rstd * gv1 + bb1;
        hs[n * HP2 + lane + 64] = (v2 - mean) * rstd * gv2 + bb2;
    }
    __syncthreads();

    const int r0 = (tid >> 4) * 4;   // 16 row-groups x 4 rows
    const int c0 = (tid & 15) * 6;   // 16 col-groups x 6 cols

    for (int cc = 0; cc < 3; cc++) {          // q, k, v (96 cols each)
        for (int idx = tid; idx < 2304; idx += 256) {
            const int row = idx / 24, c4 = idx % 24;
            *(float4*)&ws[row * 96 + c4 * 4] =
                *(const float4*)(qkvw + row * 288 + cc * 96 + c4 * 4);
        }
        __syncthreads();

        u64 acc[4][3];
        #pragma unroll
        for (int i = 0; i < 4; i++)
            #pragma unroll
            for (int j = 0; j < 3; j++) acc[i][j] = 0ull;

        gemm4x6_k96(acc, hs, r0, ws, c0);

        float* dst = (cc == 0) ? g_q : (cc == 1) ? g_k : g_v;
        #pragma unroll
        for (int i = 0; i < 4; i++) {
            float* drow = dst + (win * 64 + r0 + i) * 96 + c0;
            #pragma unroll
            for (int jp = 0; jp < 3; jp++) {
                float ax, ay; upk2(acc[i][jp], ax, ay);
                drow[2 * jp]     = ax + qkvb[cc * 96 + c0 + 2 * jp];
                drow[2 * jp + 1] = ay + qkvb[cc * 96 + c0 + 2 * jp + 1];
            }
        }
        __syncthreads();
    }
}

// ---------------------------------------------------------------------------
// K2: windowed attention, 1 block/(window,head), 64 threads.
// ---------------------------------------------------------------------------
__global__ __launch_bounds__(64) void k2_attn(const float* __restrict__ btab)
{
    __shared__ float sq[64 * 16], sk[64 * 16], sv[64 * 16];
    __shared__ float ss[64 * 65];
    __shared__ float stab[343 * 6];

    const int n    = threadIdx.x;
    const int win  = blockIdx.x / 6;
    const int head = blockIdx.x % 6;
    const int base = win * 64 * 96 + head * 16;

    #pragma unroll
    for (int j = 0; j < 4; j++) {
        ((float4*)sq)[n * 4 + j] = ((const float4*)(g_q + base + n * 96))[j];
        ((float4*)sk)[n * 4 + j] = ((const float4*)(g_k + base + n * 96))[j];
        ((float4*)sv)[n * 4 + j] = ((const float4*)(g_v + base + n * 96))[j];
    }
    for (int i = n; i < 2058; i += 64) stab[i] = btab[i];
    __syncthreads();

    u64 qp[8];
    {
        const u64* qq = (const u64*)(sq + n * 16);
        #pragma unroll
        for (int j = 0; j < 8; j++) qp[j] = qq[j];
    }
    const int iin = n >> 4, xn = (n >> 2) & 3, tn = n & 3;
    float* myrow = &ss[n * 65];

    #pragma unroll 8
    for (int m = 0; m < 64; m++) {
        const ulonglong2* kp = (const ulonglong2*)(sk + m * 16);
        u64 sa = 0ull, sb = 0ull;
        #pragma unroll
        for (int j = 0; j < 4; j++) {
            const ulonglong2 kv = kp[j];
            fma2(sa, qp[2 * j],     kv.x);
            fma2(sb, qp[2 * j + 1], kv.y);
        }
        u64 st; add2(st, sa, sb);
        float sx, sy; upk2(st, sx, sy);
        const float s = sx + sy;
        const int im = m >> 4, xm = (m >> 2) & 3, tm = m & 3;
        const int rel = ((iin - im + 3) * 7 + (xn - xm + 3)) * 7 + (tn - tm + 3);
        myrow[m] = s * 0.25f + stab[rel * 6 + head];
    }

    float mx = -1e30f;
    #pragma unroll
    for (int m = 0; m < 64; m++) mx = fmaxf(mx, myrow[m]);
    float sum = 0.0f;
    #pragma unroll 8
    for (int m = 0; m < 64; m++) {
        const float p = __expf(myrow[m] - mx);
        myrow[m] = p;
        sum += p;
    }
    const float inv = 1.0f / sum;

    u64 ov[8];
    #pragma unroll
    for (int j = 0; j < 8; j++) ov[j] = 0ull;
    #pragma unroll 8
    for (int m = 0; m < 64; m++) {
        const float p = myrow[m];
        const u64 pp = pk2(p, p);
        const ulonglong2* vp = (const ulonglong2*)(sv + m * 16);
        #pragma unroll
        for (int j = 0; j < 4; j++) {
            const ulonglong2 vv = vp[j];
            fma2(ov[2 * j],     pp, vv.x);
            fma2(ov[2 * j + 1], pp, vv.y);
        }
    }
    float* od = g_ow + base + n * 96;
    #pragma unroll
    for (int j = 0; j < 8; j++) {
        float oxv, oyv; upk2(ov[j], oxv, oyv);
        od[2 * j]     = oxv * inv;
        od[2 * j + 1] = oyv * inv;
    }
}

// ---------------------------------------------------------------------------
// K3: proj GEMM (64x96, K=96) + window reverse + un-shift + residual. 256 thr.
// ---------------------------------------------------------------------------
__global__ __launch_bounds__(256) void k3_proj(
    const float* __restrict__ x,
    const float* __restrict__ pw, const float* __restrict__ pb)
{
    extern __shared__ float dsm[];
    float* os = dsm;               // [64][HP2]
    float* ws = dsm + 64 * HP2;    // [96][96]

    const int tid = threadIdx.x;
    const int win = blockIdx.x;

    for (int idx = tid; idx < 1536; idx += 256) {
        const float4 v = ((const float4*)(g_ow + win * 64 * 96))[idx];
        const int row = idx / 24, c4 = idx % 24;
        *(float4*)&os[row * HP2 + c4 * 4] = v;
    }
    for (int idx = tid; idx < 2304; idx += 256) {
        const int row = idx / 24, c4 = idx % 24;
        *(float4*)&ws[row * 96 + c4 * 4] =
            *(const float4*)(pw + row * 96 + c4 * 4);
    }

    const int b = win >> 10, r = win & 1023;
    const int wi = r >> 8, wx = (r >> 4) & 15, wt = r & 15;
    const int r0 = (tid >> 4) * 4;
    const int c0 = (tid & 15) * 6;
    __syncthreads();

    u64 acc[4][3];
    #pragma unroll
    for (int i = 0; i < 4; i++)
        #pragma unroll
        for (int j = 0; j < 3; j++) acc[i][j] = 0ull;

    gemm4x6_k96(acc, os, r0, ws, c0);

    #pragma unroll
    for (int i = 0; i < 4; i++) {
        const int n = r0 + i;
        const int ii = n >> 4, xx = (n >> 2) & 3, tt = n & 3;
        const int gi = (wi * 4 + ii + 2) & 15;
        const int gx = (wx * 4 + xx + 2) & 63;
        const int gt = (wt * 4 + tt + 2) & 63;
        const int tok = b * 65536 + (gi * 64 + gx) * 64 + gt;
        const float* xr = x + tok * 96 + c0;
        float* dr = g_x1 + tok * 96 + c0;
        #pragma unroll
        for (int jp = 0; jp < 3; jp++) {
            float ax, ay; upk2(acc[i][jp], ax, ay);
            dr[2 * jp]     = xr[2 * jp]     + ax + pb[c0 + 2 * jp];
            dr[2 * jp + 1] = xr[2 * jp + 1] + ay + pb[c0 + 2 * jp + 1];
        }
    }
}

// ---------------------------------------------------------------------------
// K4: LN2 + MLP (96->384 gelu ->96) + residual. 64 tokens/block, 256 thr.
// smem: xs[64*HP2] | hidc[64*HP2] | ws[96*96]
// ---------------------------------------------------------------------------
__global__ __launch_bounds__(256) void k4_mlp(
    const float* __restrict__ g2, const float* __restrict__ b2,
    const float* __restrict__ w1, const float* __restrict__ b1m,
    const float* __restrict__ w2, const float* __restrict__ b2m,
    float* __restrict__ out)
{
    extern __shared__ float dsm[];
    float* xs   = dsm;
    float* hidc = dsm + 64 * HP2;
    float* ws   = dsm + 2 * 64 * HP2;

    const int tid  = threadIdx.x;
    const int lane = tid & 31;
    const int wrp  = tid >> 5;
    const int t0   = blockIdx.x * 64;

    const float gv0 = g2[lane], gv1 = g2[lane + 32], gv2 = g2[lane + 64];
    const float bb0 = b2[lane], bb1 = b2[lane + 32], bb2 = b2[lane + 64];

    for (int j = 0; j < 8; j++) {
        const int rrow = wrp * 8 + j;
        const float* row = g_x1 + (t0 + rrow) * 96;
        float v0 = row[lane], v1 = row[lane + 32], v2 = row[lane + 64];
        float s = v0 + v1 + v2;
        float q = v0 * v0 + v1 * v1 + v2 * v2;
        #pragma unroll
        for (int o = 16; o > 0; o >>= 1) {
            s += __shfl_xor_sync(0xffffffffu, s, o);
            q += __shfl_xor_sync(0xffffffffu, q, o);
        }
        const float mean = s * (1.0f / 96.0f);
        const float var  = q * (1.0f / 96.0f) - mean * mean;
        const float rstd = rsqrtf(var + 1e-5f);
        xs[rrow * HP2 + lane]      = (v0 - mean) * rstd * gv0 + bb0;
        xs[rrow * HP2 + lane + 32] = (v1 - mean) * rstd * gv1 + bb1;
        xs[rrow * HP2 + lane + 64] = (v2 - mean) * rstd * gv2 + bb2;
    }
    __syncthreads();

    const int r0 = (tid >> 4) * 4;
    const int c0 = (tid & 15) * 6;

    u64 acc[4][3];
    #pragma unroll
    for (int i = 0; i < 4; i++)
        #pragma unroll
        for (int j = 0; j < 3; j++) acc[i][j] = 0ull;

    for (int hc = 0; hc < 4; hc++) {
        // load W1 chunk [96][96]
        for (int idx = tid; idx < 2304; idx += 256) {
            const int row = idx / 24, c4 = idx % 24;
            *(float4*)&ws[row * 96 + c4 * 4] =
                *(const float4*)(w1 + row * 384 + hc * 96 + c4 * 4);
        }
        __syncthreads();

        u64 ah[4][3];
        #pragma unroll
        for (int i = 0; i < 4; i++)
            #pragma unroll
            for (int j = 0; j < 3; j++) ah[i][j] = 0ull;

        gemm4x6_k96(ah, xs, r0, ws, c0);

        #pragma unroll
        for (int i = 0; i < 4; i++)
            #pragma unroll
            for (int jp = 0; jp < 3; jp++) {
                float hx, hy; upk2(ah[i][jp], hx, hy);
                hx += b1m[hc * 96 + c0 + 2 * jp];
                hy += b1m[hc * 96 + c0 + 2 * jp + 1];
                hidc[(r0 + i) * HP2 + c0 + 2 * jp] =
                    0.5f * hx * (1.0f + erff(hx * 0.70710678118654752f));
                hidc[(r0 + i) * HP2 + c0 + 2 * jp + 1] =
                    0.5f * hy * (1.0f + erff(hy * 0.70710678118654752f));
            }
        __syncthreads();

        // load W2 chunk [96][96]
        for (int idx = tid; idx < 2304; idx += 256) {
            const int row = idx / 24, c4 = idx % 24;
            *(float4*)&ws[row * 96 + c4 * 4] =
                *(const float4*)(w2 + (hc * 96 + row) * 96 + c4 * 4);
        }
        __syncthreads();

        gemm4x6_k96(acc, hidc, r0, ws, c0);
        __syncthreads();
    }

    #pragma unroll
    for (int i = 0; i < 4; i++) {
        const int tt = t0 + r0 + i;
        const float* xr = g_x1 + tt * 96 + c0;
        float* orow = out + tt * 96 + c0;
        #pragma unroll
        for (int jp = 0; jp < 3; jp++) {
            float ax, ay; upk2(acc[i][jp], ax, ay);
            orow[2 * jp]     = xr[2 * jp]     + ax + b2m[c0 + 2 * jp];
            orow[2 * jp + 1] = xr[2 * jp + 1] + ay + b2m[c0 + 2 * jp + 1];
        }
    }
}

// ---------------------------------------------------------------------------
extern "C" void kernel_launch(void* const* d_in, const int* in_sizes, int n_in,
                              void* d_out, int out_size)
{
    (void)in_sizes; (void)n_in; (void)out_size;
    const float* x     = (const float*)d_in[0];
    const float* n1g   = (const float*)d_in[1];
    const float* n1b   = (const float*)d_in[2];
    const float* qkvw  = (const float*)d_in[3];
    const float* qkvb  = (const float*)d_in[4];
    const float* projw = (const float*)d_in[5];
    const float* projb = (const float*)d_in[6];
    const float* btab  = (const float*)d_in[7];
    const float* n2g   = (const float*)d_in[8];
    const float* n2b   = (const float*)d_in[9];
    const float* w1    = (const float*)d_in[10];
    const float* b1m   = (const float*)d_in[11];
    const float* w2    = (const float*)d_in[12];
    const float* b2m   = (const float*)d_in[13];
    float* out = (float*)d_out;

    cudaFuncSetAttribute(k1_ln_qkv, cudaFuncAttributeMaxDynamicSharedMemorySize, K1_SMEM_BYTES);
    cudaFuncSetAttribute(k3_proj,   cudaFuncAttributeMaxDynamicSharedMemorySize, K3_SMEM_BYTES);
    cudaFuncSetAttribute(k4_mlp,    cudaFuncAttributeMaxDynamicSharedMemorySize, K4_SMEM_BYTES);

    k1_ln_qkv<<<NWIN, 256, K1_SMEM_BYTES>>>(x, n1g, n1b, qkvw, qkvb);
    k2_attn  <<<NWIN * 6, 64>>>(btab);
    k3_proj  <<<NWIN, 256, K3_SMEM_BYTES>>>(x, projw, projb);
    k4_mlp   <<<NTOK / 64, 256, K4_SMEM_BYTES>>>(n2g, n2b, w1, b1m, w2, b2m, out);
}

// round 16
// speedup vs baseline: 1.3539x; 1.2770x over previous
#include <cuda_runtime.h>

// ---------------------------------------------------------------------------
// SwinTransformerBlock3D: DIM=96, HEADS=6, hd=16, WIN=4x4x4 (N=64), SHIFT=2,
// GRID=(16,64,64), B=2.  Shift == cyclic index remap (no mask needed).
// K1/K2/K3: f32x2 packed-FMA scalar path (validated).
// K4: tensor-core MLP via mma.sync.m16n8k8 tf32 (A row-major, B col-major).
// ---------------------------------------------------------------------------

#define NWIN 2048
#define NTOK 131072
#define DIMC 96
#define HP2 100            // padded row stride (A tiles): conflict-free
#define WP  104            // padded row stride (B weight panel): conflict-free

typedef unsigned long long u64;

__device__ __forceinline__ u64 pk2(float x, float y) {
    u64 r;
    asm("mov.b64 %0, {%1, %2};" : "=l"(r)
        : "r"(__float_as_uint(x)), "r"(__float_as_uint(y)));
    return r;
}
__device__ __forceinline__ void upk2(u64 v, float& x, float& y) {
    unsigned int a, b;
    asm("mov.b64 {%0, %1}, %2;" : "=r"(a), "=r"(b) : "l"(v));
    x = __uint_as_float(a); y = __uint_as_float(b);
}
__device__ __forceinline__ void fma2(u64& d, u64 a, u64 b) {
    asm("fma.rn.f32x2 %0, %1, %2, %0;" : "+l"(d) : "l"(a), "l"(b));
}
__device__ __forceinline__ void add2(u64& d, u64 a, u64 b) {
    asm("add.rn.f32x2 %0, %1, %2;" : "=l"(d) : "l"(a), "l"(b));
}
__device__ __forceinline__ float to_tf32(float x) {
    unsigned int u;
    asm("cvt.rna.tf32.f32 %0, %1;" : "=r"(u) : "f"(x));
    return __uint_as_float(u);
}
// D += A(16x8) x B(8x8), tf32 inputs as raw b32, fp32 accum.
__device__ __forceinline__ void mma_tf32(float c[4],
    unsigned a0, unsigned a1, unsigned a2, unsigned a3,
    unsigned b0, unsigned b1)
{
    asm("mma.sync.aligned.m16n8k8.row.col.f32.tf32.tf32.f32 "
        "{%0,%1,%2,%3}, {%4,%5,%6,%7}, {%8,%9}, {%0,%1,%2,%3};"
        : "+f"(c[0]), "+f"(c[1]), "+f"(c[2]), "+f"(c[3])
        : "r"(a0), "r"(a1), "r"(a2), "r"(a3), "r"(b0), "r"(b1));
}

// Scratch
__device__ float g_q [NWIN * 64 * DIMC];
__device__ float g_k [NWIN * 64 * DIMC];
__device__ float g_v [NWIN * 64 * DIMC];
__device__ float g_ow[NWIN * 64 * DIMC];
__device__ float g_x1[NTOK * DIMC];

#define K1_SMEM_BYTES ((64 * HP2 + 96 * 96) * 4)
#define K3_SMEM_BYTES ((64 * HP2 + 96 * 96) * 4)
#define K4_SMEM_BYTES ((2 * 64 * HP2 + 96 * WP) * 4)

// 4x6 microtile GEMM inner: acc[4][3] += A(4 rows) x B(6 cols), K=96.
__device__ __forceinline__ void gemm4x6_k96(
    u64 acc[4][3], const float* __restrict__ As, int r0,
    const float* __restrict__ ws, int c0)
{
    #pragma unroll 4
    for (int k4 = 0; k4 < 24; k4++) {
        float4 a4[4];
        #pragma unroll
        for (int i = 0; i < 4; i++)
            a4[i] = *(const float4*)&As[(r0 + i) * HP2 + k4 * 4];
        #pragma unroll
        for (int kk = 0; kk < 4; kk++) {
            const u64* wr = (const u64*)&ws[(k4 * 4 + kk) * 96 + c0];
            const u64 b0 = wr[0], b1 = wr[1], b2 = wr[2];
            #pragma unroll
            for (int i = 0; i < 4; i++) {
                const float a = ((const float*)&a4[i])[kk];
                const u64 pa = pk2(a, a);
                fma2(acc[i][0], pa, b0);
                fma2(acc[i][1], pa, b1);
                fma2(acc[i][2], pa, b2);
            }
        }
    }
}

// ---------------------------------------------------------------------------
// K1: LN1 + shift gather + QKV GEMM (64x288, K=96). 1 block/window, 256 thr.
// ---------------------------------------------------------------------------
__global__ __launch_bounds__(256) void k1_ln_qkv(
    const float* __restrict__ x,
    const float* __restrict__ g1, const float* __restrict__ b1,
    const float* __restrict__ qkvw, const float* __restrict__ qkvb)
{
    extern __shared__ float dsm[];
    float* hs = dsm;               // [64][HP2]
    float* ws = dsm + 64 * HP2;    // [96][96]

    const int tid  = threadIdx.x;
    const int lane = tid & 31;
    const int wrp  = tid >> 5;
    const int win  = blockIdx.x;
    const int b  = win >> 10;
    const int r  = win & 1023;
    const int wi = r >> 8, wx = (r >> 4) & 15, wt = r & 15;

    const float gv0 = g1[lane], gv1 = g1[lane + 32], gv2 = g1[lane + 64];
    const float bb0 = b1[lane], bb1 = b1[lane + 32], bb2 = b1[lane + 64];

    for (int j = 0; j < 8; j++) {
        const int n  = wrp * 8 + j;
        const int ii = n >> 4, xx = (n >> 2) & 3, tt = n & 3;
        const int gi = (wi * 4 + ii + 2) & 15;
        const int gx = (wx * 4 + xx + 2) & 63;
        const int gt = (wt * 4 + tt + 2) & 63;
        const int tok = b * 65536 + (gi * 64 + gx) * 64 + gt;
        const float* row = x + tok * 96;
        float v0 = row[lane], v1 = row[lane + 32], v2 = row[lane + 64];
        float s = v0 + v1 + v2;
        float q = v0 * v0 + v1 * v1 + v2 * v2;
        #pragma unroll
        for (int o = 16; o > 0; o >>= 1) {
            s += __shfl_xor_sync(0xffffffffu, s, o);
            q += __shfl_xor_sync(0xffffffffu, q, o);
        }
        const float mean = s * (1.0f / 96.0f);
        const float var  = q * (1.0f / 96.0f) - mean * mean;
        const float rstd = rsqrtf(var + 1e-5f);
        hs[n * HP2 + lane]      = (v0 - mean) * rstd * gv0 + bb0;
        hs[n * HP2 + lane + 32] = (v1 - mean) * rstd * gv1 + bb1;
        hs[n * HP2 + lane + 64] = (v2 - mean) * rstd * gv2 + bb2;
    }
    __syncthreads();

    const int r0 = (tid >> 4) * 4;
    const int c0 = (tid & 15) * 6;

    for (int cc = 0; cc < 3; cc++) {
        for (int idx = tid; idx < 2304; idx += 256) {
            const int row = idx / 24, c4 = idx % 24;
            *(float4*)&ws[row * 96 + c4 * 4] =
                *(const float4*)(qkvw + row * 288 + cc * 96 + c4 * 4);
        }
        __syncthreads();

        u64 acc[4][3];
        #pragma unroll
        for (int i = 0; i < 4; i++)
            #pragma unroll
            for (int j = 0; j < 3; j++) acc[i][j] = 0ull;

        gemm4x6_k96(acc, hs, r0, ws, c0);

        float* dst = (cc == 0) ? g_q : (cc == 1) ? g_k : g_v;
        #pragma unroll
        for (int i = 0; i < 4; i++) {
            float* drow = dst + (win * 64 + r0 + i) * 96 + c0;
            #pragma unroll
            for (int jp = 0; jp < 3; jp++) {
                float ax, ay; upk2(acc[i][jp], ax, ay);
                drow[2 * jp]     = ax + qkvb[cc * 96 + c0 + 2 * jp];
                drow[2 * jp + 1] = ay + qkvb[cc * 96 + c0 + 2 * jp + 1];
            }
        }
        __syncthreads();
    }
}

// ---------------------------------------------------------------------------
// K2: windowed attention, 1 block/(window,head), 64 threads.
// ---------------------------------------------------------------------------
__global__ __launch_bounds__(64) void k2_attn(const float* __restrict__ btab)
{
    __shared__ float sq[64 * 16], sk[64 * 16], sv[64 * 16];
    __shared__ float ss[64 * 65];
    __shared__ float stab[343 * 6];

    const int n    = threadIdx.x;
    const int win  = blockIdx.x / 6;
    const int head = blockIdx.x % 6;
    const int base = win * 64 * 96 + head * 16;

    #pragma unroll
    for (int j = 0; j < 4; j++) {
        ((float4*)sq)[n * 4 + j] = ((const float4*)(g_q + base + n * 96))[j];
        ((float4*)sk)[n * 4 + j] = ((const float4*)(g_k + base + n * 96))[j];
        ((float4*)sv)[n * 4 + j] = ((const float4*)(g_v + base + n * 96))[j];
    }
    for (int i = n; i < 2058; i += 64) stab[i] = btab[i];
    __syncthreads();

    u64 qp[8];
    {
        const u64* qq = (const u64*)(sq + n * 16);
        #pragma unroll
        for (int j = 0; j < 8; j++) qp[j] = qq[j];
    }
    const int iin = n >> 4, xn = (n >> 2) & 3, tn = n & 3;
    float* myrow = &ss[n * 65];

    #pragma unroll 8
    for (int m = 0; m < 64; m++) {
        const ulonglong2* kp = (const ulonglong2*)(sk + m * 16);
        u64 sa = 0ull, sb = 0ull;
        #pragma unroll
        for (int j = 0; j < 4; j++) {
            const ulonglong2 kv = kp[j];
            fma2(sa, qp[2 * j],     kv.x);
            fma2(sb, qp[2 * j + 1], kv.y);
        }
        u64 st; add2(st, sa, sb);
        float sx, sy; upk2(st, sx, sy);
        const float s = sx + sy;
        const int im = m >> 4, xm = (m >> 2) & 3, tm = m & 3;
        const int rel = ((iin - im + 3) * 7 + (xn - xm + 3)) * 7 + (tn - tm + 3);
        myrow[m] = s * 0.25f + stab[rel * 6 + head];
    }

    float mx = -1e30f;
    #pragma unroll
    for (int m = 0; m < 64; m++) mx = fmaxf(mx, myrow[m]);
    float sum = 0.0f;
    #pragma unroll 8
    for (int m = 0; m < 64; m++) {
        const float p = __expf(myrow[m] - mx);
        myrow[m] = p;
        sum += p;
    }
    const float inv = 1.0f / sum;

    u64 ov[8];
    #pragma unroll
    for (int j = 0; j < 8; j++) ov[j] = 0ull;
    #pragma unroll 8
    for (int m = 0; m < 64; m++) {
        const float p = myrow[m];
        const u64 pp = pk2(p, p);
        const ulonglong2* vp = (const ulonglong2*)(sv + m * 16);
        #pragma unroll
        for (int j = 0; j < 4; j++) {
            const ulonglong2 vv = vp[j];
            fma2(ov[2 * j],     pp, vv.x);
            fma2(ov[2 * j + 1], pp, vv.y);
        }
    }
    float* od = g_ow + base + n * 96;
    #pragma unroll
    for (int j = 0; j < 8; j++) {
        float oxv, oyv; upk2(ov[j], oxv, oyv);
        od[2 * j]     = oxv * inv;
        od[2 * j + 1] = oyv * inv;
    }
}

// ---------------------------------------------------------------------------
// K3: proj GEMM (64x96, K=96) + window reverse + un-shift + residual. 256 thr.
// ---------------------------------------------------------------------------
__global__ __launch_bounds__(256) void k3_proj(
    const float* __restrict__ x,
    const float* __restrict__ pw, const float* __restrict__ pb)
{
    extern __shared__ float dsm[];
    float* os = dsm;               // [64][HP2]
    float* ws = dsm + 64 * HP2;    // [96][96]

    const int tid = threadIdx.x;
    const int win = blockIdx.x;

    for (int idx = tid; idx < 1536; idx += 256) {
        const float4 v = ((const float4*)(g_ow + win * 64 * 96))[idx];
        const int row = idx / 24, c4 = idx % 24;
        *(float4*)&os[row * HP2 + c4 * 4] = v;
    }
    for (int idx = tid; idx < 2304; idx += 256) {
        const int row = idx / 24, c4 = idx % 24;
        *(float4*)&ws[row * 96 + c4 * 4] =
            *(const float4*)(pw + row * 96 + c4 * 4);
    }

    const int b = win >> 10, r = win & 1023;
    const int wi = r >> 8, wx = (r >> 4) & 15, wt = r & 15;
    const int r0 = (tid >> 4) * 4;
    const int c0 = (tid & 15) * 6;
    __syncthreads();

    u64 acc[4][3];
    #pragma unroll
    for (int i = 0; i < 4; i++)
        #pragma unroll
        for (int j = 0; j < 3; j++) acc[i][j] = 0ull;

    gemm4x6_k96(acc, os, r0, ws, c0);

    #pragma unroll
    for (int i = 0; i < 4; i++) {
        const int n = r0 + i;
        const int ii = n >> 4, xx = (n >> 2) & 3, tt = n & 3;
        const int gi = (wi * 4 + ii + 2) & 15;
        const int gx = (wx * 4 + xx + 2) & 63;
        const int gt = (wt * 4 + tt + 2) & 63;
        const int tok = b * 65536 + (gi * 64 + gx) * 64 + gt;
        const float* xr = x + tok * 96 + c0;
        float* dr = g_x1 + tok * 96 + c0;
        #pragma unroll
        for (int jp = 0; jp < 3; jp++) {
            float ax, ay; upk2(acc[i][jp], ax, ay);
            dr[2 * jp]     = xr[2 * jp]     + ax + pb[c0 + 2 * jp];
            dr[2 * jp + 1] = xr[2 * jp + 1] + ay + pb[c0 + 2 * jp + 1];
        }
    }
}

// ---------------------------------------------------------------------------
// K4: LN2 + MLP (96->384 gelu ->96) + residual, via mma.sync m16n8k8 tf32.
// 64 tokens/block, 256 thr (8 warps: 4 m-tiles x 2 n-halves).
// smem: xs[64][HP2] (tf32) | hidc[64][HP2] (tf32) | ws[96][WP] (tf32)
// ---------------------------------------------------------------------------
__global__ __launch_bounds__(256) void k4_mlp(
    const float* __restrict__ g2, const float* __restrict__ b2,
    const float* __restrict__ w1, const float* __restrict__ b1m,
    const float* __restrict__ w2, const float* __restrict__ b2m,
    float* __restrict__ out)
{
    extern __shared__ float dsm[];
    float* xs   = dsm;
    float* hidc = dsm + 64 * HP2;
    float* ws   = dsm + 2 * 64 * HP2;

    const int tid  = threadIdx.x;
    const int lane = tid & 31;
    const int wrp  = tid >> 5;
    const int t0   = blockIdx.x * 64;

    // LN2 -> xs (tf32-rounded values)
    {
        const float gv0 = g2[lane], gv1 = g2[lane + 32], gv2 = g2[lane + 64];
        const float bb0 = b2[lane], bb1 = b2[lane + 32], bb2 = b2[lane + 64];
        for (int j = 0; j < 8; j++) {
            const int rrow = wrp * 8 + j;
            const float* row = g_x1 + (t0 + rrow) * 96;
            float v0 = row[lane], v1 = row[lane + 32], v2 = row[lane + 64];
            float s = v0 + v1 + v2;
            float q = v0 * v0 + v1 * v1 + v2 * v2;
            #pragma unroll
            for (int o = 16; o > 0; o >>= 1) {
                s += __shfl_xor_sync(0xffffffffu, s, o);
                q += __shfl_xor_sync(0xffffffffu, q, o);
            }
            const float mean = s * (1.0f / 96.0f);
            const float var  = q * (1.0f / 96.0f) - mean * mean;
            const float rstd = rsqrtf(var + 1e-5f);
            xs[rrow * HP2 + lane]      = to_tf32((v0 - mean) * rstd * gv0 + bb0);
            xs[rrow * HP2 + lane + 32] = to_tf32((v1 - mean) * rstd * gv1 + bb1);
            xs[rrow * HP2 + lane + 64] = to_tf32((v2 - mean) * rstd * gv2 + bb2);
        }
    }
    __syncthreads();

    const int g  = lane >> 2;     // 0..7
    const int tg = lane & 3;      // 0..3
    const int m0 = (wrp >> 1) * 16;   // 4 m-tiles of 16 rows
    const int n0 = (wrp & 1) * 48;    // 2 n-halves of 48 cols

    float acc[6][4];
    #pragma unroll
    for (int i = 0; i < 6; i++)
        #pragma unroll
        for (int j = 0; j < 4; j++) acc[i][j] = 0.0f;

    for (int hc = 0; hc < 4; hc++) {
        // W1 panel [96][96] -> ws (tf32)
        for (int idx = tid; idx < 2304; idx += 256) {
            const int row = idx / 24, c4 = idx % 24;
            float4 v = *(const float4*)(w1 + row * 384 + hc * 96 + c4 * 4);
            v.x = to_tf32(v.x); v.y = to_tf32(v.y);
            v.z = to_tf32(v.z); v.w = to_tf32(v.w);
            *(float4*)&ws[row * WP + c4 * 4] = v;
        }
        __syncthreads();

        float ah[6][4];
        #pragma unroll
        for (int i = 0; i < 6; i++)
            #pragma unroll
            for (int j = 0; j < 4; j++) ah[i][j] = 0.0f;

        #pragma unroll
        for (int k8 = 0; k8 < 12; k8++) {
            const int kb = k8 * 8;
            const unsigned a0 = __float_as_uint(xs[(m0 + g)     * HP2 + kb + tg]);
            const unsigned a1 = __float_as_uint(xs[(m0 + g + 8) * HP2 + kb + tg]);
            const unsigned a2 = __float_as_uint(xs[(m0 + g)     * HP2 + kb + tg + 4]);
            const unsigned a3 = __float_as_uint(xs[(m0 + g + 8) * HP2 + kb + tg + 4]);
            #pragma unroll
            for (int n8 = 0; n8 < 6; n8++) {
                const int nc = n0 + n8 * 8 + g;
                const unsigned b0 = __float_as_uint(ws[(kb + tg)     * WP + nc]);
                const unsigned b1 = __float_as_uint(ws[(kb + tg + 4) * WP + nc]);
                mma_tf32(ah[n8], a0, a1, a2, a3, b0, b1);
            }
        }

        // bias + gelu -> hidc (tf32), float2 stores (cols 2tg,2tg+1 contiguous)
        #pragma unroll
        for (int n8 = 0; n8 < 6; n8++)
            #pragma unroll
            for (int half = 0; half < 2; half++) {
                const int row = m0 + g + half * 8;
                const int col = n0 + n8 * 8 + 2 * tg;
                float h0 = ah[n8][half * 2]     + b1m[hc * 96 + col];
                float h1 = ah[n8][half * 2 + 1] + b1m[hc * 96 + col + 1];
                h0 = 0.5f * h0 * (1.0f + erff(h0 * 0.70710678118654752f));
                h1 = 0.5f * h1 * (1.0f + erff(h1 * 0.70710678118654752f));
                float2 hv = make_float2(to_tf32(h0), to_tf32(h1));
                *(float2*)&hidc[row * HP2 + col] = hv;
            }
        __syncthreads();

        // W2 panel [96][96] -> ws (tf32)
        for (int idx = tid; idx < 2304; idx += 256) {
            const int row = idx / 24, c4 = idx % 24;
            float4 v = *(const float4*)(w2 + (hc * 96 + row) * 96 + c4 * 4);
            v.x = to_tf32(v.x); v.y = to_tf32(v.y);
            v.z = to_tf32(v.z); v.w = to_tf32(v.w);
            *(float4*)&ws[row * WP + c4 * 4] = v;
        }
        __syncthreads();

        #pragma unroll
        for (int k8 = 0; k8 < 12; k8++) {
            const int kb = k8 * 8;
            const unsigned a0 = __float_as_uint(hidc[(m0 + g)     * HP2 + kb + tg]);
            const unsigned a1 = __float_as_uint(hidc[(m0 + g + 8) * HP2 + kb + tg]);
            const unsigned a2 = __float_as_uint(hidc[(m0 + g)     * HP2 + kb + tg + 4]);
            const unsigned a3 = __float_as_uint(hidc[(m0 + g + 8) * HP2 + kb + tg + 4]);
            #pragma unroll
            for (int n8 = 0; n8 < 6; n8++) {
                const int nc = n0 + n8 * 8 + g;
                const unsigned b0 = __float_as_uint(ws[(kb + tg)     * WP + nc]);
                const unsigned b1 = __float_as_uint(ws[(kb + tg + 4) * WP + nc]);
                mma_tf32(acc[n8], a0, a1, a2, a3, b0, b1);
            }
        }
        __syncthreads();
    }

    // Epilogue: out = x1 + mlp + b2m  (float2 per C register pair)
    #pragma unroll
    for (int n8 = 0; n8 < 6; n8++)
        #pragma unroll
        for (int half = 0; half < 2; half++) {
            const int row = m0 + g + half * 8;
            const int col = n0 + n8 * 8 + 2 * tg;
            const int tt = t0 + row;
            const float2 xr = *(const float2*)(g_x1 + tt * 96 + col);
            float2 ov;
            ov.x = xr.x + acc[n8][half * 2]     + b2m[col];
            ov.y = xr.y + acc[n8][half * 2 + 1] + b2m[col + 1];
            *(float2*)(out + tt * 96 + col) = ov;
        }
}

// ---------------------------------------------------------------------------
extern "C" void kernel_launch(void* const* d_in, const int* in_sizes, int n_in,
                              void* d_out, int out_size)
{
    (void)in_sizes; (void)n_in; (void)out_size;
    const float* x     = (const float*)d_in[0];
    const float* n1g   = (const float*)d_in[1];
    const float* n1b   = (const float*)d_in[2];
    const float* qkvw  = (const float*)d_in[3];
    const float* qkvb  = (const float*)d_in[4];
    const float* projw = (const float*)d_in[5];
    const float* projb = (const float*)d_in[6];
    const float* btab  = (const float*)d_in[7];
    const float* n2g   = (const float*)d_in[8];
    const float* n2b   = (const float*)d_in[9];
    const float* w1    = (const float*)d_in[10];
    const float* b1m   = (const float*)d_in[11];
    const float* w2    = (const float*)d_in[12];
    const float* b2m   = (const float*)d_in[13];
    float* out = (float*)d_out;

    cudaFuncSetAttribute(k1_ln_qkv, cudaFuncAttributeMaxDynamicSharedMemorySize, K1_SMEM_BYTES);
    cudaFuncSetAttribute(k3_proj,   cudaFuncAttributeMaxDynamicSharedMemorySize, K3_SMEM_BYTES);
    cudaFuncSetAttribute(k4_mlp,    cudaFuncAttributeMaxDynamicSharedMemorySize, K4_SMEM_BYTES);

    k1_ln_qkv<<<NWIN, 256, K1_SMEM_BYTES>>>(x, n1g, n1b, qkvw, qkvb);
    k2_attn  <<<NWIN * 6, 64>>>(btab);
    k3_proj  <<<NWIN, 256, K3_SMEM_BYTES>>>(x, projw, projb);
    k4_mlp   <<<NTOK / 64, 256, K4_SMEM_BYTES>>>(n2g, n2b, w1, b1m, w2, b2m, out);
}

// round 17
// speedup vs baseline: 1.6288x; 1.2030x over previous
#include <cuda_runtime.h>

// ---------------------------------------------------------------------------
// SwinTransformerBlock3D: DIM=96, HEADS=6, hd=16, WIN=4x4x4 (N=64), SHIFT=2,
// GRID=(16,64,64), B=2.  Shift == cyclic index remap (no mask needed).
// K1/K3/K4 GEMMs: mma.sync.m16n8k8 tf32 (validated fragment path).
// K2: f32x2 packed-FMA attention (unchanged).
// ---------------------------------------------------------------------------

#define NWIN 2048
#define NTOK 131072
#define DIMC 96
#define HP2 100            // padded row stride (A tiles): conflict-free
#define WP  104            // padded row stride (B weight panel): conflict-free

typedef unsigned long long u64;

__device__ __forceinline__ u64 pk2(float x, float y) {
    u64 r;
    asm("mov.b64 %0, {%1, %2};" : "=l"(r)
        : "r"(__float_as_uint(x)), "r"(__float_as_uint(y)));
    return r;
}
__device__ __forceinline__ void upk2(u64 v, float& x, float& y) {
    unsigned int a, b;
    asm("mov.b64 {%0, %1}, %2;" : "=r"(a), "=r"(b) : "l"(v));
    x = __uint_as_float(a); y = __uint_as_float(b);
}
__device__ __forceinline__ void fma2(u64& d, u64 a, u64 b) {
    asm("fma.rn.f32x2 %0, %1, %2, %0;" : "+l"(d) : "l"(a), "l"(b));
}
__device__ __forceinline__ void add2(u64& d, u64 a, u64 b) {
    asm("add.rn.f32x2 %0, %1, %2;" : "=l"(d) : "l"(a), "l"(b));
}
__device__ __forceinline__ float to_tf32(float x) {
    unsigned int u;
    asm("cvt.rna.tf32.f32 %0, %1;" : "=r"(u) : "f"(x));
    return __uint_as_float(u);
}
// D += A(16x8) x B(8x8), tf32 inputs as raw b32, fp32 accum.
__device__ __forceinline__ void mma_tf32(float c[4],
    unsigned a0, unsigned a1, unsigned a2, unsigned a3,
    unsigned b0, unsigned b1)
{
    asm("mma.sync.aligned.m16n8k8.row.col.f32.tf32.tf32.f32 "
        "{%0,%1,%2,%3}, {%4,%5,%6,%7}, {%8,%9}, {%0,%1,%2,%3};"
        : "+f"(c[0]), "+f"(c[1]), "+f"(c[2]), "+f"(c[3])
        : "r"(a0), "r"(a1), "r"(a2), "r"(a3), "r"(b0), "r"(b1));
}

// Scratch
__device__ float g_q [NWIN * 64 * DIMC];
__device__ float g_k [NWIN * 64 * DIMC];
__device__ float g_v [NWIN * 64 * DIMC];
__device__ float g_ow[NWIN * 64 * DIMC];
__device__ float g_x1[NTOK * DIMC];

#define K1_SMEM_BYTES ((64 * HP2 + 96 * WP) * 4)
#define K3_SMEM_BYTES ((64 * HP2 + 96 * WP) * 4)
#define K4_SMEM_BYTES ((2 * 64 * HP2 + 96 * WP) * 4)

// MMA mainloop: C(16x48 per warp) += A[64xK96 in smem] x B[96x96 panel].
// acc[6][4]; A rows m0..m0+15 (frag rows g, g+8), B cols n0 + n8*8 + g.
__device__ __forceinline__ void mma_panel_k96(
    float acc[6][4], const float* __restrict__ As,
    const float* __restrict__ ws, int m0, int n0, int g, int tg)
{
    #pragma unroll
    for (int k8 = 0; k8 < 12; k8++) {
        const int kb = k8 * 8;
        const unsigned a0 = __float_as_uint(As[(m0 + g)     * HP2 + kb + tg]);
        const unsigned a1 = __float_as_uint(As[(m0 + g + 8) * HP2 + kb + tg]);
        const unsigned a2 = __float_as_uint(As[(m0 + g)     * HP2 + kb + tg + 4]);
        const unsigned a3 = __float_as_uint(As[(m0 + g + 8) * HP2 + kb + tg + 4]);
        #pragma unroll
        for (int n8 = 0; n8 < 6; n8++) {
            const int nc = n0 + n8 * 8 + g;
            const unsigned b0 = __float_as_uint(ws[(kb + tg)     * WP + nc]);
            const unsigned b1 = __float_as_uint(ws[(kb + tg + 4) * WP + nc]);
            mma_tf32(acc[n8], a0, a1, a2, a3, b0, b1);
        }
    }
}

// ---------------------------------------------------------------------------
// K1: LN1 + shift gather + QKV GEMM (64x288, K=96), tf32 MMA. 256 thr.
// ---------------------------------------------------------------------------
__global__ __launch_bounds__(256) void k1_ln_qkv(
    const float* __restrict__ x,
    const float* __restrict__ g1, const float* __restrict__ b1,
    const float* __restrict__ qkvw, const float* __restrict__ qkvb)
{
    extern __shared__ float dsm[];
    float* hs = dsm;               // [64][HP2] (tf32)
    float* ws = dsm + 64 * HP2;    // [96][WP]  (tf32)

    const int tid  = threadIdx.x;
    const int lane = tid & 31;
    const int wrp  = tid >> 5;
    const int win  = blockIdx.x;
    const int b  = win >> 10;
    const int r  = win & 1023;
    const int wi = r >> 8, wx = (r >> 4) & 15, wt = r & 15;

    {
        const float gv0 = g1[lane], gv1 = g1[lane + 32], gv2 = g1[lane + 64];
        const float bb0 = b1[lane], bb1 = b1[lane + 32], bb2 = b1[lane + 64];
        for (int j = 0; j < 8; j++) {
            const int n  = wrp * 8 + j;
            const int ii = n >> 4, xx = (n >> 2) & 3, tt = n & 3;
            const int gi = (wi * 4 + ii + 2) & 15;
            const int gx = (wx * 4 + xx + 2) & 63;
            const int gt = (wt * 4 + tt + 2) & 63;
            const int tok = b * 65536 + (gi * 64 + gx) * 64 + gt;
            const float* row = x + tok * 96;
            float v0 = row[lane], v1 = row[lane + 32], v2 = row[lane + 64];
            float s = v0 + v1 + v2;
            float q = v0 * v0 + v1 * v1 + v2 * v2;
            #pragma unroll
            for (int o = 16; o > 0; o >>= 1) {
                s += __shfl_xor_sync(0xffffffffu, s, o);
                q += __shfl_xor_sync(0xffffffffu, q, o);
            }
            const float mean = s * (1.0f / 96.0f);
            const float var  = q * (1.0f / 96.0f) - mean * mean;
            const float rstd = rsqrtf(var + 1e-5f);
            hs[n * HP2 + lane]      = to_tf32((v0 - mean) * rstd * gv0 + bb0);
            hs[n * HP2 + lane + 32] = to_tf32((v1 - mean) * rstd * gv1 + bb1);
            hs[n * HP2 + lane + 64] = to_tf32((v2 - mean) * rstd * gv2 + bb2);
        }
    }
    __syncthreads();

    const int g  = lane >> 2;
    const int tg = lane & 3;
    const int m0 = (wrp >> 1) * 16;
    const int n0 = (wrp & 1) * 48;

    for (int cc = 0; cc < 3; cc++) {
        for (int idx = tid; idx < 2304; idx += 256) {
            const int row = idx / 24, c4 = idx % 24;
            float4 v = *(const float4*)(qkvw + row * 288 + cc * 96 + c4 * 4);
            v.x = to_tf32(v.x); v.y = to_tf32(v.y);
            v.z = to_tf32(v.z); v.w = to_tf32(v.w);
            *(float4*)&ws[row * WP + c4 * 4] = v;
        }
        __syncthreads();

        float acc[6][4];
        #pragma unroll
        for (int i = 0; i < 6; i++)
            #pragma unroll
            for (int j = 0; j < 4; j++) acc[i][j] = 0.0f;

        mma_panel_k96(acc, hs, ws, m0, n0, g, tg);

        float* dst = (cc == 0) ? g_q : (cc == 1) ? g_k : g_v;
        #pragma unroll
        for (int n8 = 0; n8 < 6; n8++)
            #pragma unroll
            for (int half = 0; half < 2; half++) {
                const int row = m0 + g + half * 8;
                const int col = n0 + n8 * 8 + 2 * tg;
                float2 ov;
                ov.x = acc[n8][half * 2]     + qkvb[cc * 96 + col];
                ov.y = acc[n8][half * 2 + 1] + qkvb[cc * 96 + col + 1];
                *(float2*)(dst + (win * 64 + row) * 96 + col) = ov;
            }
        __syncthreads();
    }
}

// ---------------------------------------------------------------------------
// K2: windowed attention, 1 block/(window,head), 64 threads. (unchanged)
// ---------------------------------------------------------------------------
__global__ __launch_bounds__(64) void k2_attn(const float* __restrict__ btab)
{
    __shared__ float sq[64 * 16], sk[64 * 16], sv[64 * 16];
    __shared__ float ss[64 * 65];
    __shared__ float stab[343 * 6];

    const int n    = threadIdx.x;
    const int win  = blockIdx.x / 6;
    const int head = blockIdx.x % 6;
    const int base = win * 64 * 96 + head * 16;

    #pragma unroll
    for (int j = 0; j < 4; j++) {
        ((float4*)sq)[n * 4 + j] = ((const float4*)(g_q + base + n * 96))[j];
        ((float4*)sk)[n * 4 + j] = ((const float4*)(g_k + base + n * 96))[j];
        ((float4*)sv)[n * 4 + j] = ((const float4*)(g_v + base + n * 96))[j];
    }
    for (int i = n; i < 2058; i += 64) stab[i] = btab[i];
    __syncthreads();

    u64 qp[8];
    {
        const u64* qq = (const u64*)(sq + n * 16);
        #pragma unroll
        for (int j = 0; j < 8; j++) qp[j] = qq[j];
    }
    const int iin = n >> 4, xn = (n >> 2) & 3, tn = n & 3;
    float* myrow = &ss[n * 65];

    #pragma unroll 8
    for (int m = 0; m < 64; m++) {
        const ulonglong2* kp = (const ulonglong2*)(sk + m * 16);
        u64 sa = 0ull, sb = 0ull;
        #pragma unroll
        for (int j = 0; j < 4; j++) {
            const ulonglong2 kv = kp[j];
            fma2(sa, qp[2 * j],     kv.x);
            fma2(sb, qp[2 * j + 1], kv.y);
        }
        u64 st; add2(st, sa, sb);
        float sx, sy; upk2(st, sx, sy);
        const float s = sx + sy;
        const int im = m >> 4, xm = (m >> 2) & 3, tm = m & 3;
        const int rel = ((iin - im + 3) * 7 + (xn - xm + 3)) * 7 + (tn - tm + 3);
        myrow[m] = s * 0.25f + stab[rel * 6 + head];
    }

    float mx = -1e30f;
    #pragma unroll
    for (int m = 0; m < 64; m++) mx = fmaxf(mx, myrow[m]);
    float sum = 0.0f;
    #pragma unroll 8
    for (int m = 0; m < 64; m++) {
        const float p = __expf(myrow[m] - mx);
        myrow[m] = p;
        sum += p;
    }
    const float inv = 1.0f / sum;

    u64 ov[8];
    #pragma unroll
    for (int j = 0; j < 8; j++) ov[j] = 0ull;
    #pragma unroll 8
    for (int m = 0; m < 64; m++) {
        const float p = myrow[m];
        const u64 pp = pk2(p, p);
        const ulonglong2* vp = (const ulonglong2*)(sv + m * 16);
        #pragma unroll
        for (int j = 0; j < 4; j++) {
            const ulonglong2 vv = vp[j];
            fma2(ov[2 * j],     pp, vv.x);
            fma2(ov[2 * j + 1], pp, vv.y);
        }
    }
    float* od = g_ow + base + n * 96;
    #pragma unroll
    for (int j = 0; j < 8; j++) {
        float oxv, oyv; upk2(ov[j], oxv, oyv);
        od[2 * j]     = oxv * inv;
        od[2 * j + 1] = oyv * inv;
    }
}

// ---------------------------------------------------------------------------
// K3: proj GEMM (64x96, K=96) tf32 MMA + window reverse + un-shift + residual.
// ---------------------------------------------------------------------------
__global__ __launch_bounds__(256) void k3_proj(
    const float* __restrict__ x,
    const float* __restrict__ pw, const float* __restrict__ pb)
{
    extern __shared__ float dsm[];
    float* os = dsm;               // [64][HP2] (tf32)
    float* ws = dsm + 64 * HP2;    // [96][WP]  (tf32)

    const int tid = threadIdx.x;
    const int lane = tid & 31;
    const int wrp  = tid >> 5;
    const int win = blockIdx.x;

    for (int idx = tid; idx < 1536; idx += 256) {
        float4 v = ((const float4*)(g_ow + win * 64 * 96))[idx];
        v.x = to_tf32(v.x); v.y = to_tf32(v.y);
        v.z = to_tf32(v.z); v.w = to_tf32(v.w);
        const int row = idx / 24, c4 = idx % 24;
        *(float4*)&os[row * HP2 + c4 * 4] = v;
    }
    for (int idx = tid; idx < 2304; idx += 256) {
        const int row = idx / 24, c4 = idx % 24;
        float4 v = *(const float4*)(pw + row * 96 + c4 * 4);
        v.x = to_tf32(v.x); v.y = to_tf32(v.y);
        v.z = to_tf32(v.z); v.w = to_tf32(v.w);
        *(float4*)&ws[row * WP + c4 * 4] = v;
    }

    const int b = win >> 10, r = win & 1023;
    const int wi = r >> 8, wx = (r >> 4) & 15, wt = r & 15;
    const int g  = lane >> 2;
    const int tg = lane & 3;
    const int m0 = (wrp >> 1) * 16;
    const int n0 = (wrp & 1) * 48;
    __syncthreads();

    float acc[6][4];
    #pragma unroll
    for (int i = 0; i < 6; i++)
        #pragma unroll
        for (int j = 0; j < 4; j++) acc[i][j] = 0.0f;

    mma_panel_k96(acc, os, ws, m0, n0, g, tg);

    #pragma unroll
    for (int half = 0; half < 2; half++) {
        const int n = m0 + g + half * 8;
        const int ii = n >> 4, xx = (n >> 2) & 3, tt = n & 3;
        const int gi = (wi * 4 + ii + 2) & 15;
        const int gx = (wx * 4 + xx + 2) & 63;
        const int gt = (wt * 4 + tt + 2) & 63;
        const int tok = b * 65536 + (gi * 64 + gx) * 64 + gt;
        #pragma unroll
        for (int n8 = 0; n8 < 6; n8++) {
            const int col = n0 + n8 * 8 + 2 * tg;
            const float2 xr = *(const float2*)(x + tok * 96 + col);
            float2 ov;
            ov.x = xr.x + acc[n8][half * 2]     + pb[col];
            ov.y = xr.y + acc[n8][half * 2 + 1] + pb[col + 1];
            *(float2*)(g_x1 + tok * 96 + col) = ov;
        }
    }
}

// ---------------------------------------------------------------------------
// K4: LN2 + MLP (96->384 gelu ->96) + residual, tf32 MMA. (unchanged)
// ---------------------------------------------------------------------------
__global__ __launch_bounds__(256) void k4_mlp(
    const float* __restrict__ g2, const float* __restrict__ b2,
    const float* __restrict__ w1, const float* __restrict__ b1m,
    const float* __restrict__ w2, const float* __restrict__ b2m,
    float* __restrict__ out)
{
    extern __shared__ float dsm[];
    float* xs   = dsm;
    float* hidc = dsm + 64 * HP2;
    float* ws   = dsm + 2 * 64 * HP2;

    const int tid  = threadIdx.x;
    const int lane = tid & 31;
    const int wrp  = tid >> 5;
    const int t0   = blockIdx.x * 64;

    {
        const float gv0 = g2[lane], gv1 = g2[lane + 32], gv2 = g2[lane + 64];
        const float bb0 = b2[lane], bb1 = b2[lane + 32], bb2 = b2[lane + 64];
        for (int j = 0; j < 8; j++) {
            const int rrow = wrp * 8 + j;
            const float* row = g_x1 + (t0 + rrow) * 96;
            float v0 = row[lane], v1 = row[lane + 32], v2 = row[lane + 64];
            float s = v0 + v1 + v2;
            float q = v0 * v0 + v1 * v1 + v2 * v2;
            #pragma unroll
            for (int o = 16; o > 0; o >>= 1) {
                s += __shfl_xor_sync(0xffffffffu, s, o);
                q += __shfl_xor_sync(0xffffffffu, q, o);
            }
            const float mean = s * (1.0f / 96.0f);
            const float var  = q * (1.0f / 96.0f) - mean * mean;
            const float rstd = rsqrtf(var + 1e-5f);
            xs[rrow * HP2 + lane]      = to_tf32((v0 - mean) * rstd * gv0 + bb0);
            xs[rrow * HP2 + lane + 32] = to_tf32((v1 - mean) * rstd * gv1 + bb1);
            xs[rrow * HP2 + lane + 64] = to_tf32((v2 - mean) * rstd * gv2 + bb2);
        }
    }
    __syncthreads();

    const int g  = lane >> 2;
    const int tg = lane & 3;
    const int m0 = (wrp >> 1) * 16;
    const int n0 = (wrp & 1) * 48;

    float acc[6][4];
    #pragma unroll
    for (int i = 0; i < 6; i++)
        #pragma unroll
        for (int j = 0; j < 4; j++) acc[i][j] = 0.0f;

    for (int hc = 0; hc < 4; hc++) {
        for (int idx = tid; idx < 2304; idx += 256) {
            const int row = idx / 24, c4 = idx % 24;
            float4 v = *(const float4*)(w1 + row * 384 + hc * 96 + c4 * 4);
            v.x = to_tf32(v.x); v.y = to_tf32(v.y);
            v.z = to_tf32(v.z); v.w = to_tf32(v.w);
            *(float4*)&ws[row * WP + c4 * 4] = v;
        }
        __syncthreads();

        float ah[6][4];
        #pragma unroll
        for (int i = 0; i < 6; i++)
            #pragma unroll
            for (int j = 0; j < 4; j++) ah[i][j] = 0.0f;

        mma_panel_k96(ah, xs, ws, m0, n0, g, tg);

        #pragma unroll
        for (int n8 = 0; n8 < 6; n8++)
            #pragma unroll
            for (int half = 0; half < 2; half++) {
                const int row = m0 + g + half * 8;
                const int col = n0 + n8 * 8 + 2 * tg;
                float h0 = ah[n8][half * 2]     + b1m[hc * 96 + col];
                float h1 = ah[n8][half * 2 + 1] + b1m[hc * 96 + col + 1];
                h0 = 0.5f * h0 * (1.0f + erff(h0 * 0.70710678118654752f));
                h1 = 0.5f * h1 * (1.0f + erff(h1 * 0.70710678118654752f));
                float2 hv = make_float2(to_tf32(h0), to_tf32(h1));
                *(float2*)&hidc[row * HP2 + col] = hv;
            }
        __syncthreads();

        for (int idx = tid; idx < 2304; idx += 256) {
            const int row = idx / 24, c4 = idx % 24;
            float4 v = *(const float4*)(w2 + (hc * 96 + row) * 96 + c4 * 4);
            v.x = to_tf32(v.x); v.y = to_tf32(v.y);
            v.z = to_tf32(v.z); v.w = to_tf32(v.w);
            *(float4*)&ws[row * WP + c4 * 4] = v;
        }
        __syncthreads();

        mma_panel_k96(acc, hidc, ws, m0, n0, g, tg);
        __syncthreads();
    }

    #pragma unroll
    for (int n8 = 0; n8 < 6; n8++)
        #pragma unroll
        for (int half = 0; half < 2; half++) {
            const int row = m0 + g + half * 8;
            const int col = n0 + n8 * 8 + 2 * tg;
            const int tt = t0 + row;
            const float2 xr = *(const float2*)(g_x1 + tt * 96 + col);
            float2 ov;
            ov.x = xr.x + acc[n8][half * 2]     + b2m[col];
            ov.y = xr.y + acc[n8][half * 2 + 1] + b2m[col + 1];
            *(float2*)(out + tt * 96 + col) = ov;
        }
}

// ---------------------------------------------------------------------------
extern "C" void kernel_launch(void* const* d_in, const int* in_sizes, int n_in,
                              void* d_out, int out_size)
{
    (void)in_sizes; (void)n_in; (void)out_size;
    const float* x     = (const float*)d_in[0];
    const float* n1g   = (const float*)d_in[1];
    const float* n1b   = (const float*)d_in[2];
    const float* qkvw  = (const float*)d_in[3];
    const float* qkvb  = (const float*)d_in[4];
    const float* projw = (const float*)d_in[5];
    const float* projb = (const float*)d_in[6];
    const float* btab  = (const float*)d_in[7];
    const float* n2g   = (const float*)d_in[8];
    const float* n2b   = (const float*)d_in[9];
    const float* w1    = (const float*)d_in[10];
    const float* b1m   = (const float*)d_in[11];
    const float* w2    = (const float*)d_in[12];
    const float* b2m   = (const float*)d_in[13];
    float* out = (float*)d_out;

    cudaFuncSetAttribute(k1_ln_qkv, cudaFuncAttributeMaxDynamicSharedMemorySize, K1_SMEM_BYTES);
    cudaFuncSetAttribute(k3_proj,   cudaFuncAttributeMaxDynamicSharedMemorySize, K3_SMEM_BYTES);
    cudaFuncSetAttribute(k4_mlp,    cudaFuncAttributeMaxDynamicSharedMemorySize, K4_SMEM_BYTES);

    k1_ln_qkv<<<NWIN, 256, K1_SMEM_BYTES>>>(x, n1g, n1b, qkvw, qkvb);
    k2_attn  <<<NWIN * 6, 64>>>(btab);
    k3_proj  <<<NWIN, 256, K3_SMEM_BYTES>>>(x, projw, projb);
    k4_mlp   <<<NTOK / 64, 256, K4_SMEM_BYTES>>>(n2g, n2b, w1, b1m, w2, b2m, out);
}